// round 17
// baseline (speedup 1.0000x reference)
#include <cuda_runtime.h>
#include <cuda_fp16.h>

#define NN 4
#define LL 4096
#define HH 12
#define NHNH 48
#define CB 256     // rows per block (super-chunk)
#define NCB 16     // super-chunks per sequence
#define HD 768
#define EPSF 1e-6f
#define ST 72      // half-stride: 144B = 9*16B -> ldmatrix conflict-free

// Scratch: inclusive super-chunk prefixes (fp16 [m][d]); fp32 colsum prefixes; flags.
__device__ __half g_KVh[(size_t)NHNH*NCB*4096];
__device__ float  g_Ks [(size_t)NHNH*NCB*64];
__device__ int    g_flag[NHNH*NCB];

__device__ __forceinline__ float phi(float x) { return x > 0.f ? x + 1.f : __expf(x); }

__device__ __forceinline__ unsigned h2(float a, float b) {
    __half2 h = __floats2half2_rn(a, b);
    return *(unsigned*)&h;
}

__device__ __forceinline__ void ldsm_x4(unsigned* r, unsigned addr) {
    asm volatile("ldmatrix.sync.aligned.m8n8.x4.shared.b16 {%0,%1,%2,%3}, [%4];"
        : "=r"(r[0]), "=r"(r[1]), "=r"(r[2]), "=r"(r[3]) : "r"(addr));
}
__device__ __forceinline__ void ldsm_x4_t(unsigned* r, unsigned addr) {
    asm volatile("ldmatrix.sync.aligned.m8n8.x4.trans.shared.b16 {%0,%1,%2,%3}, [%4];"
        : "=r"(r[0]), "=r"(r[1]), "=r"(r[2]), "=r"(r[3]) : "r"(addr));
}
__device__ __forceinline__ void ldsm_x2(unsigned* r, unsigned addr) {
    asm volatile("ldmatrix.sync.aligned.m8n8.x2.shared.b16 {%0,%1}, [%2];"
        : "=r"(r[0]), "=r"(r[1]) : "r"(addr));
}
__device__ __forceinline__ void ldsm_x2_t(unsigned* r, unsigned addr) {
    asm volatile("ldmatrix.sync.aligned.m8n8.x2.trans.shared.b16 {%0,%1}, [%2];"
        : "=r"(r[0]), "=r"(r[1]) : "r"(addr));
}
__device__ __forceinline__ void mma16(float* d, const unsigned* a, const unsigned* b) {
    asm volatile(
        "mma.sync.aligned.m16n8k16.row.col.f32.f16.f16.f32 "
        "{%0,%1,%2,%3},{%4,%5,%6,%7},{%8,%9},{%0,%1,%2,%3};\n"
        : "+f"(d[0]), "+f"(d[1]), "+f"(d[2]), "+f"(d[3])
        : "r"(a[0]), "r"(a[1]), "r"(a[2]), "r"(a[3]), "r"(b[0]), "r"(b[1]));
}

__global__ void resetK() {
    int i = blockIdx.x * 256 + threadIdx.x;
    if (i < NHNH*NCB) g_flag[i] = 0;
}

// ---------------------------------------------------------------------------
// Fused single-pass chained scan, 256 rows/block.  bid = c*NHNH + nh.
// ---------------------------------------------------------------------------
__global__ __launch_bounds__(256) void fusedK(const float* __restrict__ q,
                                              const float* __restrict__ k,
                                              const float* __restrict__ v,
                                              float* __restrict__ out) {
    extern __shared__ __align__(16) __half smb[];
    __half* k_s = smb;               // [s][d]  256 x ST  (phi applied)
    __half* v_s = smb + 256*ST;      // [s][m]  256 x ST, col 64 = 1, 65..71 = 0
    __half* q_s = smb + 512*ST;      // [l][d]  128 x ST  (rows 0..127, later 128..255)
    __half* P_s = smb + 640*ST;      // [l][s]  64 x ST
    __half* S_s = smb + 704*ST;      // [m][d]  72 x ST, row 64 = Kpre, 65..71 = 0
    float*  z_s = (float*)(smb + 776*ST);   // 64 z + 128 ks partials

    int bid = blockIdx.x;
    int c = bid / NHNH, nh = bid - c*NHNH;
    int n = nh / HH, h = nh % HH;
    int l0 = c * CB;
    int t = threadIdx.x, lane = t & 31, w = t >> 5;

    // ---- stage k,v (256 rows) and q rows 0..127 ----
    for (int idx = t; idx < 4096; idx += 256) {
        int l = idx >> 4, j = (idx & 15) << 2;
        size_t g = ((size_t)(n*LL + l0 + l))*HD + h*64 + j;
        float4 b = *(const float4*)(k + g);
        *(uint2*)(k_s + l*ST + j) = make_uint2(h2(phi(b.x), phi(b.y)), h2(phi(b.z), phi(b.w)));
        float4 c4 = *(const float4*)(v + g);
        *(uint2*)(v_s + l*ST + j) = make_uint2(h2(c4.x, c4.y), h2(c4.z, c4.w));
    }
    for (int idx = t; idx < 2048; idx += 256) {
        int l = idx >> 4, j = (idx & 15) << 2;
        size_t g = ((size_t)(n*LL + l0 + l))*HD + h*64 + j;
        float4 a = *(const float4*)(q + g);
        *(uint2*)(q_s + l*ST + j) = make_uint2(h2(phi(a.x), phi(a.y)), h2(phi(a.z), phi(a.w)));
    }
    if (t < 256) {
        *(uint2*)(v_s + t*ST + 64) = make_uint2(h2(1.f, 0.f), 0u);
        *(uint2*)(v_s + t*ST + 68) = make_uint2(0u, 0u);
    }
    for (int idx = t; idx < 448; idx += 256)
        S_s[(65 + (idx >> 6))*ST + (idx & 63)] = __ushort_as_half(0);
    __syncthreads();

    // warp strips / lane addressing
    int r0 = (w >> 1) * 16;
    int odd = w & 1;
    int nb = odd * 32;
    unsigned qb = (unsigned)__cvta_generic_to_shared(q_s);
    unsigned kb = (unsigned)__cvta_generic_to_shared(k_s);
    unsigned vb = (unsigned)__cvta_generic_to_shared(v_s);
    unsigned Pb = (unsigned)__cvta_generic_to_shared(P_s);
    unsigned Sb = (unsigned)__cvta_generic_to_shared(S_s);
    int an_row = r0 + (lane & 15);
    int an_col = (lane >> 4) << 3;
    int bn_row = ((lane >> 4) << 3) + (lane & 7);
    int bn_col = ((lane >> 3) & 1) << 3;
    int bt_row = (((lane >> 3) & 1) << 3) + (lane & 7);
    int bt_col = (lane >> 4) << 3;
    int at_row = ((lane >> 4) << 3) + (lane & 7);
    int at_col = r0 + ((lane >> 3) & 1) * 8;
    int rowb = r0 + (lane >> 2);

    // ---- full 256-row aggregate: KVagg[m][d], and phiK colsum partials ----
    float agg[4][4];
#pragma unroll
    for (int i = 0; i < 4; i++)
#pragma unroll
        for (int j = 0; j < 4; j++) agg[i][j] = 0.f;
#pragma unroll
    for (int k0 = 0; k0 < 256; k0 += 16) {
        unsigned a[4]; ldsm_x4_t(a, vb + ((k0 + at_row)*ST + at_col)*2);
        unsigned b01[4]; ldsm_x4_t(b01, kb + ((k0 + bt_row)*ST + nb + bt_col)*2);
        unsigned b23[4]; ldsm_x4_t(b23, kb + ((k0 + bt_row)*ST + nb + 16 + bt_col)*2);
        mma16(agg[0], a, b01); mma16(agg[1], a, b01 + 2);
        mma16(agg[2], a, b23); mma16(agg[3], a, b23 + 2);
    }
    if (t < 128) {                       // ks partials: [half][col]
        int col = t & 63, half = t >> 6;
        float s0 = 0.f;
#pragma unroll 8
        for (int s = half*128; s < half*128 + 128; s++) s0 += __half2float(k_s[s*ST + col]);
        z_s[64 + t] = s0;
    }
    __syncthreads();

    // ---- wait for predecessor, stage S_pre, publish inclusive quickly ----
    if (c > 0) {
        if (t == 0) {
            const int* fp = g_flag + bid - NHNH;
            int f;
            do {
                asm volatile("ld.global.acquire.gpu.b32 %0, [%1];" : "=r"(f) : "l"(fp));
                if (!f) __nanosleep(40);
            } while (!f);
        }
        __syncthreads();
        const __half* pred = g_KVh + (size_t)(bid - NHNH) * 4096;
        __half* mine = g_KVh + (size_t)bid * 4096;
#pragma unroll
        for (int i = 0; i < 4; i++) {
            int col = nb + i*8 + (lane & 3)*2;
            unsigned p0 = __ldcg((const unsigned*)(pred + rowb*64 + col));
            unsigned p1 = __ldcg((const unsigned*)(pred + (rowb+8)*64 + col));
            *(unsigned*)(S_s + rowb*ST + col)     = p0;
            *(unsigned*)(S_s + (rowb+8)*ST + col) = p1;
            float2 f0 = __half22float2(*(__half2*)&p0);
            float2 f1 = __half22float2(*(__half2*)&p1);
            *(unsigned*)(mine + rowb*64 + col)     = h2(f0.x + agg[i][0], f0.y + agg[i][1]);
            *(unsigned*)(mine + (rowb+8)*64 + col) = h2(f1.x + agg[i][2], f1.y + agg[i][3]);
        }
        if (t < 64) {
            float pks = __ldcg(g_Ks + (size_t)(bid - NHNH)*64 + t);
            S_s[64*ST + t] = __float2half_rn(pks);
            g_Ks[(size_t)bid*64 + t] = pks + z_s[64 + t] + z_s[128 + t];
        }
    } else {
        __half* mine = g_KVh + (size_t)bid * 4096;
#pragma unroll
        for (int i = 0; i < 4; i++) {
            int col = nb + i*8 + (lane & 3)*2;
            *(unsigned*)(S_s + rowb*ST + col)     = 0u;
            *(unsigned*)(S_s + (rowb+8)*ST + col) = 0u;
            *(unsigned*)(mine + rowb*64 + col)     = h2(agg[i][0], agg[i][1]);
            *(unsigned*)(mine + (rowb+8)*64 + col) = h2(agg[i][2], agg[i][3]);
        }
        if (t < 64) {
            S_s[64*ST + t] = __ushort_as_half(0);
            g_Ks[(size_t)bid*64 + t] = z_s[64 + t] + z_s[128 + t];
        }
    }
    __syncthreads();
    if (t == 0)
        asm volatile("st.global.release.gpu.b32 [%0], %1;" :: "l"(g_flag + bid), "r"(1));

    // ---- four 64-row sub-tiles sharing in-smem state ----
    for (int tile = 0; tile < 4; tile++) {
        int ro = tile << 6;
        int qo = ro & 127;      // q_s holds rows 0..127 (tiles 0,1) then 128..255

        if (tile == 2) {
            // reload q rows 128..255 (prior sync at end of tile1 covers q_s reads)
            for (int idx = t; idx < 2048; idx += 256) {
                int l = idx >> 4, j = (idx & 15) << 2;
                size_t g = ((size_t)(n*LL + l0 + 128 + l))*HD + h*64 + j;
                float4 a = *(const float4*)(q + g);
                *(uint2*)(q_s + l*ST + j) = make_uint2(h2(phi(a.x), phi(a.y)), h2(phi(a.z), phi(a.w)));
            }
            __syncthreads();
        }

        float pacc[4][4], oacc[5][4];
#pragma unroll
        for (int i = 0; i < 4; i++)
#pragma unroll
            for (int j = 0; j < 4; j++) pacc[i][j] = 0.f;
#pragma unroll
        for (int i = 0; i < 5; i++)
#pragma unroll
            for (int j = 0; j < 4; j++) oacc[i][j] = 0.f;

        // Loop 1: P = Qt Kt^T  and  O = Qt S_ext (z via Kpre row 64)
#pragma unroll
        for (int k0 = 0; k0 < 64; k0 += 16) {
            unsigned a[4]; ldsm_x4(a, qb + ((qo + an_row)*ST + k0 + an_col)*2);
            unsigned bk[4], bk2[4];
            ldsm_x4(bk,  kb + ((ro + nb + bn_row)*ST + k0 + bn_col)*2);
            ldsm_x4(bk2, kb + ((ro + nb + 16 + bn_row)*ST + k0 + bn_col)*2);
            mma16(pacc[0], a, bk);  mma16(pacc[1], a, bk + 2);
            mma16(pacc[2], a, bk2); mma16(pacc[3], a, bk2 + 2);
            unsigned bs[4], bs2[4];
            ldsm_x4(bs,  Sb + ((nb + bn_row)*ST + k0 + bn_col)*2);
            ldsm_x4(bs2, Sb + ((nb + 16 + bn_row)*ST + k0 + bn_col)*2);
            mma16(oacc[0], a, bs);  mma16(oacc[1], a, bs + 2);
            mma16(oacc[2], a, bs2); mma16(oacc[3], a, bs2 + 2);
            if (odd) {
                unsigned bz[2]; ldsm_x2(bz, Sb + ((64 + (lane & 7))*ST + k0 + bn_col)*2);
                mma16(oacc[4], a, bz);
            }
        }

        // causal mask (relative) + fp16 store of P
#pragma unroll
        for (int i = 0; i < 4; i++) {
            int colb = nb + i*8 + (lane & 3)*2;
            float p0 = (colb     <= rowb) ? pacc[i][0] : 0.f;
            float p1 = (colb + 1 <= rowb) ? pacc[i][1] : 0.f;
            *(unsigned*)(P_s + rowb*ST + colb) = h2(p0, p1);
            int row1 = rowb + 8;
            float p2 = (colb     <= row1) ? pacc[i][2] : 0.f;
            float p3 = (colb + 1 <= row1) ? pacc[i][3] : 0.f;
            *(unsigned*)(P_s + row1*ST + colb) = h2(p2, p3);
        }
        __syncthreads();

        // Loop 2: O += P * Vt_ext
#pragma unroll
        for (int k0 = 0; k0 < 64; k0 += 16) {
            unsigned a[4]; ldsm_x4(a, Pb + (an_row*ST + k0 + an_col)*2);
            unsigned bv[4], bv2[4];
            ldsm_x4_t(bv,  vb + ((ro + k0 + bt_row)*ST + nb + bt_col)*2);
            ldsm_x4_t(bv2, vb + ((ro + k0 + bt_row)*ST + nb + 16 + bt_col)*2);
            mma16(oacc[0], a, bv);  mma16(oacc[1], a, bv + 2);
            mma16(oacc[2], a, bv2); mma16(oacc[3], a, bv2 + 2);
            if (odd) {
                unsigned bz[2]; ldsm_x2_t(bz, vb + ((ro + k0 + (lane & 15))*ST + 64)*2);
                mma16(oacc[4], a, bz);
            }
        }

        if (odd && (lane & 3) == 0) {
            z_s[rowb]     = oacc[4][0] + EPSF;
            z_s[rowb + 8] = oacc[4][2] + EPSF;
        }
        __syncthreads();

        {
            float rz0 = __frcp_rn(z_s[rowb]);
            float rz1 = __frcp_rn(z_s[rowb + 8]);
#pragma unroll
            for (int i = 0; i < 4; i++) {
                int col = nb + i*8 + (lane & 3)*2;
                size_t g0 = ((size_t)(n*LL + l0 + ro + rowb))*HD + h*64 + col;
                size_t g1 = ((size_t)(n*LL + l0 + ro + rowb + 8))*HD + h*64 + col;
                *(float2*)(out + g0) = make_float2(oacc[i][0]*rz0, oacc[i][1]*rz0);
                *(float2*)(out + g1) = make_float2(oacc[i][2]*rz1, oacc[i][3]*rz1);
            }
        }

        if (tile < 3) {
            // S += Vt^T phiKt; Kpre += colsum phiKt
            float uacc[4][4];
#pragma unroll
            for (int i = 0; i < 4; i++)
#pragma unroll
                for (int j = 0; j < 4; j++) uacc[i][j] = 0.f;
#pragma unroll
            for (int k0 = 0; k0 < 64; k0 += 16) {
                unsigned ua[4]; ldsm_x4_t(ua, vb + ((ro + k0 + at_row)*ST + at_col)*2);
                unsigned ub[4], ub2[4];
                ldsm_x4_t(ub,  kb + ((ro + k0 + bt_row)*ST + nb + bt_col)*2);
                ldsm_x4_t(ub2, kb + ((ro + k0 + bt_row)*ST + nb + 16 + bt_col)*2);
                mma16(uacc[0], ua, ub);  mma16(uacc[1], ua, ub + 2);
                mma16(uacc[2], ua, ub2); mma16(uacc[3], ua, ub2 + 2);
            }
#pragma unroll
            for (int i = 0; i < 4; i++) {
                int col = nb + i*8 + (lane & 3)*2;
                unsigned* p0 = (unsigned*)(S_s + rowb*ST + col);
                float2 f0 = __half22float2(*(__half2*)p0);
                *p0 = h2(f0.x + uacc[i][0], f0.y + uacc[i][1]);
                unsigned* p1 = (unsigned*)(S_s + (rowb + 8)*ST + col);
                float2 f1 = __half22float2(*(__half2*)p1);
                *p1 = h2(f1.x + uacc[i][2], f1.y + uacc[i][3]);
            }
            if (t < 64) {
                float s0 = 0.f;
#pragma unroll 8
                for (int s = ro; s < ro + 64; s++) s0 += __half2float(k_s[s*ST + t]);
                S_s[64*ST + t] = __float2half_rn(__half2float(S_s[64*ST + t]) + s0);
            }
            __syncthreads();
        }
    }
}

// ---------------------------------------------------------------------------
extern "C" void kernel_launch(void* const* d_in, const int* in_sizes, int n_in,
                              void* d_out, int out_size) {
    const float* q = (const float*)d_in[0];
    const float* k = (const float*)d_in[1];
    const float* v = (const float*)d_in[2];
    float* out = (float*)d_out;

    const int smemC = 776*ST*2 + 192*4;   // 112,512 B -> 2 CTAs/SM
    cudaFuncSetAttribute(fusedK, cudaFuncAttributeMaxDynamicSharedMemorySize, smemC);

    resetK<<<3, 256>>>();
    fusedK<<<NHNH*NCB, 256, smemC>>>(q, k, v, out);
}